// round 8
// baseline (speedup 1.0000x reference)
#include <cuda_runtime.h>
#include <cuda_bf16.h>
#include <math.h>
#include <stdint.h>

// Problem constants
#define BSZ  16384
#define HD   256
#define GXD  70
#define GYD  70
#define SWIN 2
#define NKW  25   // 5x5 window

// ---------------- scratch (static device memory, no allocations) ----------------
// g_AH row (1536): [hidHi(256)|hidHi|hidLo | featHi(256)|featHi|featLo]
// g_W1 row jn=4u+g (1536): [hhHi|hhLo|hhHi | ihHi|ihLo|ihHi] of orig row g*256+u
// g_Wout row (1536): [hi(512)|lo(512)|hi(512)]
// g_Cext row (1536): [mixHi(256)|qHi|mixHi|qHi|mixLo|qLo]
__device__ __align__(16) __nv_bfloat16 g_AH  [(size_t)BSZ * 1536];
__device__ __align__(16) __nv_bfloat16 g_W1  [(size_t)1024 * 1536];
__device__ __align__(16) __nv_bfloat16 g_Wout[(size_t)256 * 1536];
__device__ __align__(16) __nv_bfloat16 g_Cext[(size_t)BSZ * 1536];
__device__ float g_sg[(size_t)BSZ * 256];
__device__ float g_ug[(size_t)BSZ * 256];
__device__ float g_bc [1024];   // b_ih+b_hh, gate-interleaved order
__device__ float g_bhn[256];    // b_hh n-gate

__device__ __forceinline__ float sigmoidf_(float x) {
    return 1.0f / (1.0f + expf(-x));
}

__device__ __forceinline__ uint32_t smem_u32(const void* p) {
    uint32_t a;
    asm("{ .reg .u64 t; cvta.to.shared.u64 t, %1; cvt.u32.u64 %0, t; }" : "=r"(a) : "l"(p));
    return a;
}

__device__ __forceinline__ void ldsm_x4(uint32_t addr, uint32_t& r0, uint32_t& r1,
                                        uint32_t& r2, uint32_t& r3) {
    asm volatile("ldmatrix.sync.aligned.m8n8.x4.shared.b16 {%0,%1,%2,%3}, [%4];"
                 : "=r"(r0), "=r"(r1), "=r"(r2), "=r"(r3) : "r"(addr));
}

__device__ __forceinline__ void mma16816(float& d0, float& d1, float& d2, float& d3,
                                         uint32_t a0, uint32_t a1, uint32_t a2, uint32_t a3,
                                         uint32_t b0, uint32_t b1) {
    asm volatile("mma.sync.aligned.m16n8k16.row.col.f32.bf16.bf16.f32 "
                 "{%0,%1,%2,%3}, {%4,%5,%6,%7}, {%8,%9}, {%0,%1,%2,%3};"
                 : "+f"(d0), "+f"(d1), "+f"(d2), "+f"(d3)
                 : "r"(a0), "r"(a1), "r"(a2), "r"(a3), "r"(b0), "r"(b1));
}

#define CP_ASYNC16(dst, src) \
    asm volatile("cp.async.cg.shared.global [%0], [%1], 16;" :: "r"(dst), "l"(src))
#define CP_COMMIT() asm volatile("cp.async.commit_group;")
#define CP_WAIT2()  asm volatile("cp.async.wait_group 2;")

// Swizzled tile: 128 rows x 128B (64 bf16), unit' = unit ^ (row&7). 16KB/tile.
#define TILEB   16384
#define STAGEB  32768   // A tile + B tile
#define NSTAGE  3
#define SMEM_GEMM  (NSTAGE * STAGEB)           // 96KB (tgemm2)
#define SMEM_GEMM1 (SMEM_GEMM + 16384)         // +16KB h_n table (tgemm1)

// ---------------- conversion kernels -------------------------------------------
// A-side split per half: [hi | hi | lo]. z=0: feat -> base 768; z=1: hidden -> base 0.
__global__ __launch_bounds__(256) void conv_ah_kernel(const float* __restrict__ input_tensor,
                                                      const float* __restrict__ hidden) {
    size_t i = (size_t)blockIdx.x * 256 + threadIdx.x;   // BSZ*128 threads, 2 cols each
    size_t b = i >> 7;
    int c = (int)(i & 127) * 2;
    const float* src; int stride, base;
    if (blockIdx.z == 0) { src = input_tensor; stride = 258; base = 768; }
    else                 { src = hidden;       stride = 256; base = 0;   }
    float2 v = *(const float2*)(src + b * stride + c);
    __nv_bfloat16 h0 = __float2bfloat16(v.x);
    __nv_bfloat16 h1 = __float2bfloat16(v.y);
    __nv_bfloat16 l0 = __float2bfloat16(v.x - __bfloat162float(h0));
    __nv_bfloat16 l1 = __float2bfloat16(v.y - __bfloat162float(h1));
    __nv_bfloat162 hh; hh.x = h0; hh.y = h1;
    __nv_bfloat162 ll; ll.x = l0; ll.y = l1;
    __nv_bfloat16* d = g_AH + b * 1536 + base + c;
    *(__nv_bfloat162*)(d)       = hh;
    *(__nv_bfloat162*)(d + 256) = hh;
    *(__nv_bfloat162*)(d + 512) = ll;
}

// W-side split per half: [hi | lo | hi]. z=0: w_hh -> base 0; z=1: w_ih -> base 768;
// z=2: g_Wout (K=512 pattern).
__global__ __launch_bounds__(256) void conv_w_kernel(const float* __restrict__ w_ih,
                                                     const float* __restrict__ w_hh,
                                                     const float* __restrict__ w_out) {
    const int sel = blockIdx.z;
    size_t e = ((size_t)blockIdx.x * 256 + threadIdx.x) * 2;
    if (sel <= 1) {                       // g_W1: gate-interleaved rows
        if (blockIdx.x >= 512) return;
        int rn = (int)(e >> 8), k = (int)(e & 255);
        int orig = (rn & 3) * 256 + (rn >> 2);
        const float* src = ((sel == 0) ? w_hh : w_ih) + (size_t)orig * 256 + k;
        __nv_bfloat16* dst = g_W1 + (size_t)rn * 1536 + (sel ? 768 : 0) + k;
        float2 v = *(const float2*)src;
        __nv_bfloat16 h0 = __float2bfloat16(v.x), h1 = __float2bfloat16(v.y);
        __nv_bfloat16 l0 = __float2bfloat16(v.x - __bfloat162float(h0));
        __nv_bfloat16 l1 = __float2bfloat16(v.y - __bfloat162float(h1));
        __nv_bfloat162 hh; hh.x = h0; hh.y = h1;
        __nv_bfloat162 ll; ll.x = l0; ll.y = l1;
        *(__nv_bfloat162*)(dst)       = hh;
        *(__nv_bfloat162*)(dst + 256) = ll;
        *(__nv_bfloat162*)(dst + 512) = hh;
    } else {                              // g_Wout from w_out (256 x 512)
        if (blockIdx.x >= 256) return;
        int r = (int)(e >> 9), k = (int)(e & 511);
        float2 v = *(const float2*)(w_out + (size_t)r * 512 + k);
        __nv_bfloat16 h0 = __float2bfloat16(v.x), h1 = __float2bfloat16(v.y);
        __nv_bfloat16 l0 = __float2bfloat16(v.x - __bfloat162float(h0));
        __nv_bfloat16 l1 = __float2bfloat16(v.y - __bfloat162float(h1));
        __nv_bfloat162 hh; hh.x = h0; hh.y = h1;
        __nv_bfloat162 ll; ll.x = l0; ll.y = l1;
        __nv_bfloat16* d = g_Wout + (size_t)r * 1536 + k;
        *(__nv_bfloat162*)(d)        = hh;
        *(__nv_bfloat162*)(d + 512)  = ll;
        *(__nv_bfloat162*)(d + 1024) = hh;
    }
}

__global__ void conv_bias_kernel(const float* __restrict__ b_ih,
                                 const float* __restrict__ b_hh) {
    int i = blockIdx.x * 256 + threadIdx.x;
    if (i < 1024) {
        int orig = (i & 3) * 256 + (i >> 2);
        g_bc[i] = b_ih[orig] + b_hh[orig];
    } else {
        int u = i - 1024;
        g_bhn[u] = b_hh[512 + u];
    }
}

// ---------------- pipelined mma.sync GEMM mainloop (R6-proven scheme) -----------
// acc[mt][nt][4]: warp tile 32(m) x 64(n); 8 warps in 4(m) x 2(n).
// If SNAP>0: after chunk SNAP-1, odd-tig threads store their n-gate partial sums
// (fragment elements {0,2}) to the smem table hn_s[row*32+unit]. No register cost.
template <int KEXT, int SNAP>
__device__ __forceinline__ void mma_gemm_main(const __nv_bfloat16* __restrict__ A,
                                              const __nv_bfloat16* __restrict__ W,
                                              char* smem, float (&acc)[2][8][4]) {
    const int tid = threadIdx.x;
    const int wid = tid >> 5, lane = tid & 31;
    const int wm = (wid & 3) * 32;
    const int wn = (wid >> 2) * 64;
    const uint32_t sbase = smem_u32(smem);

    const int crow0 = tid >> 3, cunit = tid & 7;
    const __nv_bfloat16* ga = A + (size_t)(blockIdx.y * 128) * KEXT + cunit * 8;
    const __nv_bfloat16* gw = W + (size_t)(blockIdx.x * 128) * KEXT + cunit * 8;

    int rowA[2], rowB[4];
#pragma unroll
    for (int mt = 0; mt < 2; mt++)
        rowA[mt] = wm + mt * 16 + (lane & 8) + (lane & 7);
#pragma unroll
    for (int nt2 = 0; nt2 < 4; nt2++)
        rowB[nt2] = wn + nt2 * 16 + ((lane >> 4) & 1) * 8 + (lane & 7);
    const int uA = lane >> 4;
    const int uB = (lane >> 3) & 1;

    constexpr int NC = KEXT / 64;

    auto issue = [&](int ch) {
        const int s = ch % NSTAGE;
        const uint32_t dA = sbase + s * STAGEB;
        const uint32_t dB = dA + TILEB;
#pragma unroll
        for (int j = 0; j < 4; j++) {
            const int row = crow0 + j * 32;
            const uint32_t off = (uint32_t)row * 128 + (uint32_t)((cunit ^ (row & 7)) * 16);
            const size_t gofs = (size_t)row * KEXT + ch * 64;
            CP_ASYNC16(dA + off, ga + gofs);
            CP_ASYNC16(dB + off, gw + gofs);
        }
        CP_COMMIT();
    };

    issue(0);
    issue(1);
#pragma unroll 1
    for (int ch = 0; ch < NC; ch++) {
        if (ch + 2 < NC) issue(ch + 2); else CP_COMMIT();
        CP_WAIT2();
        __syncthreads();
        const int s = ch % NSTAGE;
        const uint32_t aB = sbase + s * STAGEB;
        const uint32_t bB = aB + TILEB;
#pragma unroll
        for (int ks = 0; ks < 4; ks++) {
            uint32_t a[2][4], b[4][4];
#pragma unroll
            for (int mt = 0; mt < 2; mt++) {
                const int u = ks * 2 + uA;
                const uint32_t addr = aB + (uint32_t)rowA[mt] * 128
                                    + (uint32_t)((u ^ (rowA[mt] & 7)) * 16);
                ldsm_x4(addr, a[mt][0], a[mt][1], a[mt][2], a[mt][3]);
            }
#pragma unroll
            for (int nt2 = 0; nt2 < 4; nt2++) {
                const int u = ks * 2 + uB;
                const uint32_t addr = bB + (uint32_t)rowB[nt2] * 128
                                    + (uint32_t)((u ^ (rowB[nt2] & 7)) * 16);
                ldsm_x4(addr, b[nt2][0], b[nt2][1], b[nt2][2], b[nt2][3]);
            }
#pragma unroll
            for (int mt = 0; mt < 2; mt++)
#pragma unroll
                for (int nt = 0; nt < 8; nt++) {
                    const uint32_t b0 = b[nt >> 1][(nt & 1) * 2 + 0];
                    const uint32_t b1 = b[nt >> 1][(nt & 1) * 2 + 1];
                    mma16816(acc[mt][nt][0], acc[mt][nt][1], acc[mt][nt][2], acc[mt][nt][3],
                             a[mt][0], a[mt][1], a[mt][2], a[mt][3], b0, b1);
                }
        }
        if (SNAP > 0 && ch == SNAP - 1) {
            // store n-gate partials to smem table (one-time; no mainloop registers)
            float* hn_s = (float*)(smem + SMEM_GEMM);
            const int gid = lane >> 2, tig = lane & 3;
            if (tig & 1) {
#pragma unroll
                for (int mt = 0; mt < 2; mt++)
#pragma unroll
                    for (int nt = 0; nt < 8; nt++) {
                        const int ul = (wn + nt * 8 + 2 * tig) >> 2;   // 0..31
#pragma unroll
                        for (int half = 0; half < 2; half++) {
                            const int rl = wm + mt * 16 + gid + half * 8;
                            hn_s[rl * 32 + ul] = acc[mt][nt][half * 2];
                        }
                    }
            }
        }
        __syncthreads();
    }
}

// ---------------- main GEMM: all gate sums + fused gate math --------------------
__global__ __launch_bounds__(256) void tgemm1_kernel() {
    extern __shared__ char smem[];
    float acc[2][8][4];
#pragma unroll
    for (int mt = 0; mt < 2; mt++)
#pragma unroll
        for (int nt = 0; nt < 8; nt++)
#pragma unroll
            for (int e = 0; e < 4; e++) acc[mt][nt][e] = 0.0f;

    // hidden = chunks 0..11, feat = chunks 12..23; snapshot h_n after hidden part
    mma_gemm_main<1536, 12>(g_AH, g_W1, smem, acc);

    float* hn_s = (float*)(smem + SMEM_GEMM);            // [128][32], written at ch=11
    __nv_bfloat16* qh_s = (__nv_bfloat16*)smem;          // [128][32]
    __nv_bfloat16* ql_s = qh_s + 4096;                   // [128][32]
    float* sg_s = (float*)(smem + 16384);                // [128][32]
    float* ug_s = sg_s + 4096;                           // [128][32]

    const int tid = threadIdx.x, wid = tid >> 5, lane = tid & 31;
    const int wm = (wid & 3) * 32, wn = (wid >> 2) * 64;
    const int gid = lane >> 2, tig = lane & 3;
    const int srcLane = lane & ~1;
#pragma unroll
    for (int mt = 0; mt < 2; mt++) {
#pragma unroll
        for (int nt = 0; nt < 8; nt++) {
            const int col = wn + nt * 8 + 2 * tig;           // 0..127 within tile
            const float bc0 = g_bc[blockIdx.x * 128 + col];
            const float bc1 = g_bc[blockIdx.x * 128 + col + 1];
#pragma unroll
            for (int half = 0; half < 2; half++) {
                const int rl = wm + mt * 16 + gid + half * 8;  // 0..127
                float v0 = acc[mt][nt][half * 2 + 0] + bc0;
                float v1 = acc[mt][nt][half * 2 + 1] + bc1;
                float sig0 = sigmoidf_(v0);
                float sig1 = sigmoidf_(v1);
                float rg = __shfl_sync(0xffffffffu, sig0, srcLane);
                float ug = __shfl_sync(0xffffffffu, sig1, srcLane);
                if (tig & 1) {   // this thread's even col is the n-gate of unit ul
                    const int ul = col >> 2;                   // 0..31
                    const int u  = blockIdx.x * 32 + ul;
                    float hn = hn_s[rl * 32 + ul] + g_bhn[u];
                    float q  = tanhf(v0 + (rg - 1.0f) * hn);
                    __nv_bfloat16 qh = __float2bfloat16(q);
                    qh_s[rl * 32 + ul] = qh;
                    ql_s[rl * 32 + ul] = __float2bfloat16(q - __bfloat162float(qh));
                    sg_s[rl * 32 + ul] = sig1;   // spatialgate
                    ug_s[rl * 32 + ul] = ug;     // updategate
                }
            }
        }
    }
    __syncthreads();
    // coalesced global writes
    for (int idx = tid; idx < 4096; idx += 256) {
        const int rl = idx >> 5, ul = idx & 31;
        const size_t r = blockIdx.y * 128 + rl;
        const int u = blockIdx.x * 32 + ul;
        __nv_bfloat16 qh = qh_s[idx], ql = ql_s[idx];
        g_Cext[r * 1536 + 256 + u]  = qh;
        g_Cext[r * 1536 + 768 + u]  = qh;
        g_Cext[r * 1536 + 1280 + u] = ql;
        g_sg[r * 256 + u] = sg_s[idx];
        g_ug[r * 256 + u] = ug_s[idx];
    }
}

// ---------------- kernel: attention over 5x5 context (vectorized) ---------------
__global__ __launch_bounds__(256) void phaseB_kernel(
    const float* __restrict__ input_tensor,
    const float* __restrict__ memory) {
    const int b = blockIdx.x;
    const int t = threadIdx.x;

    __shared__ float q_s[HD];
    __shared__ float ctx[NKW][HD];
    __shared__ float attn_p[NKW][2];
    __shared__ float w_s[NKW];

    __nv_bfloat16* crow = g_Cext + (size_t)b * 1536;
    float q = __bfloat162float(crow[256 + t]) + __bfloat162float(crow[1280 + t]);
    q_s[t] = q;

    int gx = (int)input_tensor[(size_t)b * 258 + 256] + SWIN;
    int gy = (int)input_tensor[(size_t)b * 258 + 257] + SWIN;
    gx = min(max(gx, 0), GXD - 1);
    gy = min(max(gy, 0), GYD - 1);

    __syncthreads();   // q_s ready for the fused dot

    // fused gather + partial attention dot (float4); 64 threads per k-row
    const int kq  = t >> 6;          // 0..3 row group
    const int cq  = (t & 63) * 4;    // float4 column base
    const int lane = t & 31;
    const int sub  = (t >> 5) & 1;
    float4 q4 = *(const float4*)(q_s + cq);
#pragma unroll
    for (int base = 0; base < 28; base += 4) {
        const int k = base + kq;
        if (k < NKW) {               // uniform per warp (64-thread groups)
            int xi = min(max(gx + k / 5 - SWIN, 0), GXD - 1);
            int yi = min(max(gy + k % 5 - SWIN, 0), GYD - 1);
            float4 v = *(const float4*)(memory + ((size_t)xi * GYD + yi) * HD + cq);
            *(float4*)(&ctx[k][cq]) = v;
            float part = v.x * q4.x + v.y * q4.y + v.z * q4.z + v.w * q4.w;
#pragma unroll
            for (int off = 16; off; off >>= 1)
                part += __shfl_xor_sync(0xffffffffu, part, off);
            if (lane == 0) attn_p[k][sub] = part;
        }
    }
    __syncthreads();

    // softmax over 25 (one warp), attn==0 -> -inf, NaN -> 0 semantics
    if (t < 32) {
        float v = (lane < NKW) ? (attn_p[lane][0] + attn_p[lane][1]) : -INFINITY;
        if (v == 0.0f) v = -INFINITY;
        float mx = v;
#pragma unroll
        for (int off = 16; off; off >>= 1)
            mx = fmaxf(mx, __shfl_xor_sync(0xffffffffu, mx, off));
        float e = (mx == -INFINITY) ? 0.0f : expf(v - mx);
        float den = e;
#pragma unroll
        for (int off = 16; off; off >>= 1)
            den += __shfl_xor_sync(0xffffffffu, den, off);
        float wv = (den > 0.0f) ? (e / den) : 0.0f;
        if (lane < NKW) w_s[lane] = wv;
    }
    __syncthreads();

    float mix = 0.0f;
#pragma unroll
    for (int k = 0; k < NKW; k++)
        mix = fmaf(w_s[k], ctx[k][t], mix);

    __nv_bfloat16 mh = __float2bfloat16(mix);
    __nv_bfloat16 ml = __float2bfloat16(mix - __bfloat162float(mh));
    crow[t]        = mh;
    crow[512 + t]  = mh;
    crow[1024 + t] = ml;
}

// ---------------- kernel: output GEMM + fused GRU epilogue ----------------------
__global__ __launch_bounds__(256) void tgemm2_kernel(const float* __restrict__ b_out,
                                                     const float* __restrict__ hidden,
                                                     float* __restrict__ out) {
    extern __shared__ char smem[];

    float acc[2][8][4];
#pragma unroll
    for (int mt = 0; mt < 2; mt++)
#pragma unroll
        for (int nt = 0; nt < 8; nt++)
#pragma unroll
            for (int e = 0; e < 4; e++) acc[mt][nt][e] = 0.0f;

    mma_gemm_main<1536, 0>(g_Cext, g_Wout, smem, acc);

    const int wid = threadIdx.x >> 5, lane = threadIdx.x & 31;
    const int wm = (wid & 3) * 32, wn = (wid >> 2) * 64;
    const int gid = lane >> 2, tig = lane & 3;
#pragma unroll
    for (int mt = 0; mt < 2; mt++) {
        const int rbase = blockIdx.y * 128 + wm + mt * 16 + gid;
#pragma unroll
        for (int nt = 0; nt < 8; nt++) {
            const int c = blockIdx.x * 128 + wn + nt * 8 + 2 * tig;
            float2 bv = *(const float2*)(b_out + c);
#pragma unroll
            for (int half = 0; half < 2; half++) {
                const int r = rbase + half * 8;
                const __nv_bfloat16* crow = g_Cext + (size_t)r * 1536;
                __nv_bfloat162 qh2 = *(const __nv_bfloat162*)(crow + 256 + c);
                __nv_bfloat162 ql2 = *(const __nv_bfloat162*)(crow + 1280 + c);
                float2 sg2 = *(const float2*)(g_sg + (size_t)r * 256 + c);
                float2 ug2 = *(const float2*)(g_ug + (size_t)r * 256 + c);
                float2 h2  = *(const float2*)(hidden + (size_t)r * 256 + c);
                float q0 = __bfloat162float(qh2.x) + __bfloat162float(ql2.x);
                float q1 = __bfloat162float(qh2.y) + __bfloat162float(ql2.y);
                float v0 = acc[mt][nt][half * 2 + 0] + bv.x;
                float v1 = acc[mt][nt][half * 2 + 1] + bv.y;
                float a0 = tanhf(v0), a1 = tanhf(v1);
                float cu0 = q0 + sg2.x * a0;
                float cu1 = q1 + sg2.y * a1;
                float2 o;
                o.x = cu0 + ug2.x * (h2.x - cu0);
                o.y = cu1 + ug2.y * (h2.y - cu1);
                *(float2*)(out + (size_t)r * 256 + c) = o;
            }
        }
    }
}

// ---------------- launch ---------------------------------------------------------
extern "C" void kernel_launch(void* const* d_in, const int* in_sizes, int n_in,
                              void* d_out, int out_size) {
    const float* input_tensor = (const float*)d_in[0];  // (B, 258)
    const float* hidden       = (const float*)d_in[1];  // (B, 256)
    const float* w_ih         = (const float*)d_in[2];  // (1024, 256)
    const float* b_ih         = (const float*)d_in[3];  // (1024)
    const float* w_hh         = (const float*)d_in[4];  // (1024, 256)
    const float* b_hh         = (const float*)d_in[5];  // (1024)
    const float* w_out        = (const float*)d_in[6];  // (256, 512)
    const float* b_out        = (const float*)d_in[7];  // (256)
    const float* memory       = (const float*)d_in[8];  // (70, 70, 256)
    float* out = (float*)d_out;                         // (B, 256)

    // Host-side, idempotent, not a stream op (capture-safe).
    cudaFuncSetAttribute(tgemm1_kernel, cudaFuncAttributeMaxDynamicSharedMemorySize, SMEM_GEMM1);
    cudaFuncSetAttribute(tgemm2_kernel, cudaFuncAttributeMaxDynamicSharedMemorySize, SMEM_GEMM);

    conv_ah_kernel<<<dim3(8192, 1, 2), 256>>>(input_tensor, hidden);
    conv_w_kernel<<<dim3(512, 1, 3), 256>>>(w_ih, w_hh, w_out);
    conv_bias_kernel<<<5, 256>>>(b_ih, b_hh);
    tgemm1_kernel<<<dim3(8, 128), 256, SMEM_GEMM1>>>();
    phaseB_kernel<<<BSZ, 256>>>(input_tensor, memory);
    tgemm2_kernel<<<dim3(2, 128), 256, SMEM_GEMM>>>(b_out, hidden, out);
}

// round 9
// speedup vs baseline: 1.0456x; 1.0456x over previous
#include <cuda_runtime.h>
#include <cuda_bf16.h>
#include <math.h>
#include <stdint.h>

// Problem constants
#define BSZ  16384
#define HD   256
#define GXD  70
#define GYD  70
#define SWIN 2
#define NKW  25   // 5x5 window

// ---------------- scratch (static device memory, no allocations) ----------------
// bf16 split-extended operands: A-side layout [hi | hi | lo], W-side [hi | lo | hi]
__device__ __align__(16) __nv_bfloat16 g_Aext[(size_t)BSZ * 768];
__device__ __align__(16) __nv_bfloat16 g_Hext[(size_t)BSZ * 768];
__device__ __align__(16) __nv_bfloat16 g_Wih [(size_t)1024 * 768];
__device__ __align__(16) __nv_bfloat16 g_Whh [(size_t)1024 * 768];
__device__ __align__(16) __nv_bfloat16 g_Wout[(size_t)256 * 1536];
__device__ __align__(16) __nv_bfloat16 g_Cext[(size_t)BSZ * 1536];
__device__ float g_gi[(size_t)BSZ * 1024];
__device__ float g_gh[(size_t)BSZ * 1024];
__device__ float g_sg[(size_t)BSZ * 256];
__device__ float g_ug[(size_t)BSZ * 256];

__device__ __forceinline__ float sigmoidf_(float x) {
    return 1.0f / (1.0f + expf(-x));
}

__device__ __forceinline__ uint32_t smem_u32(const void* p) {
    uint32_t a;
    asm("{ .reg .u64 t; cvta.to.shared.u64 t, %1; cvt.u32.u64 %0, t; }" : "=r"(a) : "l"(p));
    return a;
}

__device__ __forceinline__ void ldsm_x4(uint32_t addr, uint32_t& r0, uint32_t& r1,
                                        uint32_t& r2, uint32_t& r3) {
    asm volatile("ldmatrix.sync.aligned.m8n8.x4.shared.b16 {%0,%1,%2,%3}, [%4];"
                 : "=r"(r0), "=r"(r1), "=r"(r2), "=r"(r3) : "r"(addr));
}

__device__ __forceinline__ void mma16816(float& d0, float& d1, float& d2, float& d3,
                                         uint32_t a0, uint32_t a1, uint32_t a2, uint32_t a3,
                                         uint32_t b0, uint32_t b1) {
    asm volatile("mma.sync.aligned.m16n8k16.row.col.f32.bf16.bf16.f32 "
                 "{%0,%1,%2,%3}, {%4,%5,%6,%7}, {%8,%9}, {%0,%1,%2,%3};"
                 : "+f"(d0), "+f"(d1), "+f"(d2), "+f"(d3)
                 : "r"(a0), "r"(a1), "r"(a2), "r"(a3), "r"(b0), "r"(b1));
}

#define CP_ASYNC16(dst, src) \
    asm volatile("cp.async.cg.shared.global [%0], [%1], 16;" :: "r"(dst), "l"(src))
#define CP_COMMIT() asm volatile("cp.async.commit_group;")
#define CP_WAIT2()  asm volatile("cp.async.wait_group 2;")

// Swizzled tile: rows x 128B (64 bf16), unit' = unit ^ (row&7).
#define TILEB   16384                  // 128-row tile
#define STAGEB  32768                  // A tile + B tile (128x128 CTA)
#define NSTAGE  3
#define SMEM_BYTES (NSTAGE * STAGEB)   // 96KB (tgemm1)

// tgemm2 (64x128 CTA): A tile 8KB + B tile 16KB
#define TILEB2A 8192
#define STAGEB2 24576
#define SMEM_BYTES2 (NSTAGE * STAGEB2) // 72KB

// ---------------- conversion kernels (fp32 -> split bf16, extended K) ----------
// A-side layout per row: [hi(K) | hi(K) | lo(K)]
__global__ __launch_bounds__(256) void conv_ah_kernel(const float* __restrict__ input_tensor,
                                                      const float* __restrict__ hidden) {
    size_t i = (size_t)blockIdx.x * 256 + threadIdx.x;   // BSZ*128 threads, 2 cols each
    size_t b = i >> 7;
    int c = (int)(i & 127) * 2;
    const float* src; __nv_bfloat16* dst; int stride;
    if (blockIdx.z == 0) { src = input_tensor; dst = g_Aext; stride = 258; }
    else                 { src = hidden;       dst = g_Hext; stride = 256; }
    float2 v = *(const float2*)(src + b * stride + c);
    __nv_bfloat16 h0 = __float2bfloat16(v.x);
    __nv_bfloat16 h1 = __float2bfloat16(v.y);
    __nv_bfloat16 l0 = __float2bfloat16(v.x - __bfloat162float(h0));
    __nv_bfloat16 l1 = __float2bfloat16(v.y - __bfloat162float(h1));
    __nv_bfloat162 hh; hh.x = h0; hh.y = h1;
    __nv_bfloat162 ll; ll.x = l0; ll.y = l1;
    __nv_bfloat16* d = dst + b * 768 + c;
    *(__nv_bfloat162*)(d)       = hh;
    *(__nv_bfloat162*)(d + 256) = hh;
    *(__nv_bfloat162*)(d + 512) = ll;
}

// W-side layout per row: [hi(K) | lo(K) | hi(K)]; z selects {w_ih, w_hh, w_out}
__global__ __launch_bounds__(256) void conv_w_kernel(const float* __restrict__ w_ih,
                                                     const float* __restrict__ w_hh,
                                                     const float* __restrict__ w_out) {
    const int sel = blockIdx.z;
    const float* src = (sel == 0) ? w_ih : (sel == 1) ? w_hh : w_out;
    __nv_bfloat16* dst = (sel == 0) ? g_Wih : (sel == 1) ? g_Whh : g_Wout;
    const int K = (sel == 2) ? 512 : 256;
    const int nblk = (sel == 2) ? 256 : 512;
    if (blockIdx.x >= nblk) return;
    size_t e = ((size_t)blockIdx.x * 256 + threadIdx.x) * 2;
    size_t r = e / (size_t)K;
    int k = (int)(e % (size_t)K);
    float2 v = *(const float2*)(src + r * K + k);
    __nv_bfloat16 h0 = __float2bfloat16(v.x);
    __nv_bfloat16 h1 = __float2bfloat16(v.y);
    __nv_bfloat16 l0 = __float2bfloat16(v.x - __bfloat162float(h0));
    __nv_bfloat16 l1 = __float2bfloat16(v.y - __bfloat162float(h1));
    __nv_bfloat162 hh; hh.x = h0; hh.y = h1;
    __nv_bfloat162 ll; ll.x = l0; ll.y = l1;
    __nv_bfloat16* d = dst + r * (size_t)(3 * K) + k;
    *(__nv_bfloat162*)(d)         = hh;
    *(__nv_bfloat162*)(d + K)     = ll;
    *(__nv_bfloat162*)(d + 2 * K) = hh;
}

// ---------------- pipelined mma.sync GEMM mainloop (128x128 CTA, proven) --------
// acc[mt][nt][4]: warp tile 32(m) x 64(n); 8 warps in 4(m) x 2(n).
template <int KEXT>
__device__ __forceinline__ void mma_gemm_main(const __nv_bfloat16* __restrict__ A,
                                              const __nv_bfloat16* __restrict__ W,
                                              char* smem, float (&acc)[2][8][4]) {
    const int tid = threadIdx.x;
    const int wid = tid >> 5, lane = tid & 31;
    const int wm = (wid & 3) * 32;
    const int wn = (wid >> 2) * 64;
    const uint32_t sbase = smem_u32(smem);

    const int crow0 = tid >> 3, cunit = tid & 7;
    const __nv_bfloat16* ga = A + (size_t)(blockIdx.y * 128) * KEXT + cunit * 8;
    const __nv_bfloat16* gw = W + (size_t)(blockIdx.x * 128) * KEXT + cunit * 8;

    int rowA[2], rowB[4];
#pragma unroll
    for (int mt = 0; mt < 2; mt++)
        rowA[mt] = wm + mt * 16 + (lane & 8) + (lane & 7);
#pragma unroll
    for (int nt2 = 0; nt2 < 4; nt2++)
        rowB[nt2] = wn + nt2 * 16 + ((lane >> 4) & 1) * 8 + (lane & 7);
    const int uA = lane >> 4;
    const int uB = (lane >> 3) & 1;

    constexpr int NC = KEXT / 64;

    auto issue = [&](int ch) {
        const int s = ch % NSTAGE;
        const uint32_t dA = sbase + s * STAGEB;
        const uint32_t dB = dA + TILEB;
#pragma unroll
        for (int j = 0; j < 4; j++) {
            const int row = crow0 + j * 32;
            const uint32_t off = (uint32_t)row * 128 + (uint32_t)((cunit ^ (row & 7)) * 16);
            const size_t gofs = (size_t)row * KEXT + ch * 64;
            CP_ASYNC16(dA + off, ga + gofs);
            CP_ASYNC16(dB + off, gw + gofs);
        }
        CP_COMMIT();
    };

    issue(0);
    issue(1);
#pragma unroll 1
    for (int ch = 0; ch < NC; ch++) {
        if (ch + 2 < NC) issue(ch + 2); else CP_COMMIT();
        CP_WAIT2();
        __syncthreads();
        const int s = ch % NSTAGE;
        const uint32_t aB = sbase + s * STAGEB;
        const uint32_t bB = aB + TILEB;
#pragma unroll
        for (int ks = 0; ks < 4; ks++) {
            uint32_t a[2][4], b[4][4];
#pragma unroll
            for (int mt = 0; mt < 2; mt++) {
                const int u = ks * 2 + uA;
                const uint32_t addr = aB + (uint32_t)rowA[mt] * 128
                                    + (uint32_t)((u ^ (rowA[mt] & 7)) * 16);
                ldsm_x4(addr, a[mt][0], a[mt][1], a[mt][2], a[mt][3]);
            }
#pragma unroll
            for (int nt2 = 0; nt2 < 4; nt2++) {
                const int u = ks * 2 + uB;
                const uint32_t addr = bB + (uint32_t)rowB[nt2] * 128
                                    + (uint32_t)((u ^ (rowB[nt2] & 7)) * 16);
                ldsm_x4(addr, b[nt2][0], b[nt2][1], b[nt2][2], b[nt2][3]);
            }
#pragma unroll
            for (int mt = 0; mt < 2; mt++)
#pragma unroll
                for (int nt = 0; nt < 8; nt++) {
                    const uint32_t b0 = b[nt >> 1][(nt & 1) * 2 + 0];
                    const uint32_t b1 = b[nt >> 1][(nt & 1) * 2 + 1];
                    mma16816(acc[mt][nt][0], acc[mt][nt][1], acc[mt][nt][2], acc[mt][nt][3],
                             a[mt][0], a[mt][1], a[mt][2], a[mt][3], b0, b1);
                }
        }
        __syncthreads();
    }
}

// ---------------- pipelined mainloop, 64x128 CTA (tgemm2) -----------------------
// acc[mt][nt][4]: warp tile 32(m) x 32(n); 8 warps in 2(m) x 4(n).
template <int KEXT>
__device__ __forceinline__ void mma_gemm_main64(const __nv_bfloat16* __restrict__ A,
                                                const __nv_bfloat16* __restrict__ W,
                                                char* smem, float (&acc)[2][4][4]) {
    const int tid = threadIdx.x;
    const int wid = tid >> 5, lane = tid & 31;
    const int wm = (wid & 1) * 32;
    const int wn = (wid >> 1) * 32;
    const uint32_t sbase = smem_u32(smem);

    const int crow0 = tid >> 3, cunit = tid & 7;
    const __nv_bfloat16* ga = A + (size_t)(blockIdx.y * 64) * KEXT + cunit * 8;
    const __nv_bfloat16* gw = W + (size_t)(blockIdx.x * 128) * KEXT + cunit * 8;

    int rowA[2], rowB[2];
#pragma unroll
    for (int mt = 0; mt < 2; mt++)
        rowA[mt] = wm + mt * 16 + (lane & 8) + (lane & 7);
#pragma unroll
    for (int nt2 = 0; nt2 < 2; nt2++)
        rowB[nt2] = wn + nt2 * 16 + ((lane >> 4) & 1) * 8 + (lane & 7);
    const int uA = lane >> 4;
    const int uB = (lane >> 3) & 1;

    constexpr int NC = KEXT / 64;

    auto issue = [&](int ch) {
        const int s = ch % NSTAGE;
        const uint32_t dA = sbase + s * STAGEB2;
        const uint32_t dB = dA + TILEB2A;
#pragma unroll
        for (int j = 0; j < 2; j++) {   // A: 64 rows, 2 per thread
            const int row = crow0 + j * 32;
            const uint32_t off = (uint32_t)row * 128 + (uint32_t)((cunit ^ (row & 7)) * 16);
            CP_ASYNC16(dA + off, ga + (size_t)row * KEXT + ch * 64);
        }
#pragma unroll
        for (int j = 0; j < 4; j++) {   // B: 128 rows, 4 per thread
            const int row = crow0 + j * 32;
            const uint32_t off = (uint32_t)row * 128 + (uint32_t)((cunit ^ (row & 7)) * 16);
            CP_ASYNC16(dB + off, gw + (size_t)row * KEXT + ch * 64);
        }
        CP_COMMIT();
    };

    issue(0);
    issue(1);
#pragma unroll 1
    for (int ch = 0; ch < NC; ch++) {
        if (ch + 2 < NC) issue(ch + 2); else CP_COMMIT();
        CP_WAIT2();
        __syncthreads();
        const int s = ch % NSTAGE;
        const uint32_t aB = sbase + s * STAGEB2;
        const uint32_t bB = aB + TILEB2A;
#pragma unroll
        for (int ks = 0; ks < 4; ks++) {
            uint32_t a[2][4], b[2][4];
#pragma unroll
            for (int mt = 0; mt < 2; mt++) {
                const int u = ks * 2 + uA;
                const uint32_t addr = aB + (uint32_t)rowA[mt] * 128
                                    + (uint32_t)((u ^ (rowA[mt] & 7)) * 16);
                ldsm_x4(addr, a[mt][0], a[mt][1], a[mt][2], a[mt][3]);
            }
#pragma unroll
            for (int nt2 = 0; nt2 < 2; nt2++) {
                const int u = ks * 2 + uB;
                const uint32_t addr = bB + (uint32_t)rowB[nt2] * 128
                                    + (uint32_t)((u ^ (rowB[nt2] & 7)) * 16);
                ldsm_x4(addr, b[nt2][0], b[nt2][1], b[nt2][2], b[nt2][3]);
            }
#pragma unroll
            for (int mt = 0; mt < 2; mt++)
#pragma unroll
                for (int nt = 0; nt < 4; nt++) {
                    const uint32_t b0 = b[nt >> 1][(nt & 1) * 2 + 0];
                    const uint32_t b1 = b[nt >> 1][(nt & 1) * 2 + 1];
                    mma16816(acc[mt][nt][0], acc[mt][nt][1], acc[mt][nt][2], acc[mt][nt][3],
                             a[mt][0], a[mt][1], a[mt][2], a[mt][3], b0, b1);
                }
        }
        __syncthreads();
    }
}

// ---------------- kernel: gi / gh GEMMs (z=0: feature, z=1: hidden) -------------
__global__ __launch_bounds__(256) void tgemm1_kernel(const float* __restrict__ b_ih,
                                                     const float* __restrict__ b_hh) {
    extern __shared__ char smem[];
    const __nv_bfloat16* A = blockIdx.z ? g_Hext : g_Aext;
    const __nv_bfloat16* W = blockIdx.z ? g_Whh  : g_Wih;
    const float* bias      = blockIdx.z ? b_hh   : b_ih;
    float* C               = blockIdx.z ? g_gh   : g_gi;

    float acc[2][8][4];
#pragma unroll
    for (int mt = 0; mt < 2; mt++)
#pragma unroll
        for (int nt = 0; nt < 8; nt++)
#pragma unroll
            for (int e = 0; e < 4; e++) acc[mt][nt][e] = 0.0f;

    mma_gemm_main<768>(A, W, smem, acc);

    const int wid = threadIdx.x >> 5, lane = threadIdx.x & 31;
    const int wm = (wid & 3) * 32, wn = (wid >> 2) * 64;
    const int gid = lane >> 2, tig = lane & 3;
#pragma unroll
    for (int mt = 0; mt < 2; mt++) {
        const int r = blockIdx.y * 128 + wm + mt * 16 + gid;
#pragma unroll
        for (int nt = 0; nt < 8; nt++) {
            const int c = blockIdx.x * 128 + wn + nt * 8 + 2 * tig;
            float2 bv = *(const float2*)(bias + c);
            float2 v0 = { acc[mt][nt][0] + bv.x, acc[mt][nt][1] + bv.y };
            float2 v1 = { acc[mt][nt][2] + bv.x, acc[mt][nt][3] + bv.y };
            *(float2*)(C + (size_t)r * 1024 + c)       = v0;
            *(float2*)(C + (size_t)(r + 8) * 1024 + c) = v1;
        }
    }
}

// ---------------- kernel: gates + attention over 5x5 context ------------------
__global__ __launch_bounds__(256) void phaseB_kernel(
    const float* __restrict__ input_tensor,
    const float* __restrict__ memory) {
    const int b = blockIdx.x;
    const int t = threadIdx.x;

    __shared__ float q_s[HD];
    __shared__ float ctx[NKW][HD];
    __shared__ float attn_p[NKW][2];
    __shared__ float w_s[NKW];

    const float* gi = g_gi + (size_t)b * 1024;
    const float* gh = g_gh + (size_t)b * 1024;
    float i_r = gi[t],       h_r = gh[t];
    float i_i = gi[256 + t], h_i = gh[256 + t];
    float i_n = gi[512 + t], h_n = gh[512 + t];
    float i_s = gi[768 + t], h_s = gh[768 + t];

    float rg = sigmoidf_(i_r + h_r);
    float ug = sigmoidf_(i_i + h_i);
    float sg = sigmoidf_(i_s + h_s);
    float q  = tanhf(i_n + rg * h_n);
    q_s[t] = q;
    g_sg[(size_t)b * HD + t] = sg;
    g_ug[(size_t)b * HD + t] = ug;

    int gx = (int)input_tensor[(size_t)b * 258 + 256] + SWIN;
    int gy = (int)input_tensor[(size_t)b * 258 + 257] + SWIN;
    gx = min(max(gx, 0), GXD - 1);
    gy = min(max(gy, 0), GYD - 1);

    __syncthreads();   // q_s ready for the fused dot

    // fused gather + partial attention dot (float4); 64 threads per k-row
    const int kq  = t >> 6;          // 0..3 row group
    const int cq  = (t & 63) * 4;    // float4 column base
    const int lane = t & 31;
    const int sub  = (t >> 5) & 1;
    float4 q4 = *(const float4*)(q_s + cq);
#pragma unroll
    for (int base = 0; base < 28; base += 4) {
        const int k = base + kq;
        if (k < NKW) {               // uniform per warp (64-thread groups)
            int xi = min(max(gx + k / 5 - SWIN, 0), GXD - 1);
            int yi = min(max(gy + k % 5 - SWIN, 0), GYD - 1);
            float4 v = *(const float4*)(memory + ((size_t)xi * GYD + yi) * HD + cq);
            *(float4*)(&ctx[k][cq]) = v;
            float part = v.x * q4.x + v.y * q4.y + v.z * q4.z + v.w * q4.w;
#pragma unroll
            for (int off = 16; off; off >>= 1)
                part += __shfl_xor_sync(0xffffffffu, part, off);
            if (lane == 0) attn_p[k][sub] = part;
        }
    }
    __syncthreads();

    // softmax over 25 (one warp), attn==0 -> -inf, NaN -> 0 semantics
    if (t < 32) {
        float v = (lane < NKW) ? (attn_p[lane][0] + attn_p[lane][1]) : -INFINITY;
        if (v == 0.0f) v = -INFINITY;
        float mx = v;
#pragma unroll
        for (int off = 16; off; off >>= 1)
            mx = fmaxf(mx, __shfl_xor_sync(0xffffffffu, mx, off));
        float e = (mx == -INFINITY) ? 0.0f : expf(v - mx);
        float den = e;
#pragma unroll
        for (int off = 16; off; off >>= 1)
            den += __shfl_xor_sync(0xffffffffu, den, off);
        float wv = (den > 0.0f) ? (e / den) : 0.0f;
        if (lane < NKW) w_s[lane] = wv;
    }

    // q-dependent Cext writes (all 256 threads; independent of mix)
    __nv_bfloat16* crow = g_Cext + (size_t)b * 1536;
    {
        __nv_bfloat16 qh = __float2bfloat16(q);
        __nv_bfloat16 ql = __float2bfloat16(q - __bfloat162float(qh));
        crow[256 + t]  = qh;
        crow[768 + t]  = qh;
        crow[1280 + t] = ql;
    }
    __syncthreads();

    // mix = sum_k w_k * ctx[k][:] — vectorized float4 on 64 threads
    if (t < 64) {
        const int c0 = t * 4;
        float4 m4 = make_float4(0.0f, 0.0f, 0.0f, 0.0f);
#pragma unroll
        for (int k = 0; k < NKW; k++) {
            const float w = w_s[k];
            float4 c4 = *(const float4*)(&ctx[k][c0]);
            m4.x = fmaf(w, c4.x, m4.x);
            m4.y = fmaf(w, c4.y, m4.y);
            m4.z = fmaf(w, c4.z, m4.z);
            m4.w = fmaf(w, c4.w, m4.w);
        }
        float mv[4] = { m4.x, m4.y, m4.z, m4.w };
        __nv_bfloat16 mh[4], ml[4];
#pragma unroll
        for (int e = 0; e < 4; e++) {
            mh[e] = __float2bfloat16(mv[e]);
            ml[e] = __float2bfloat16(mv[e] - __bfloat162float(mh[e]));
        }
        __nv_bfloat162 h01; h01.x = mh[0]; h01.y = mh[1];
        __nv_bfloat162 h23; h23.x = mh[2]; h23.y = mh[3];
        __nv_bfloat162 l01; l01.x = ml[0]; l01.y = ml[1];
        __nv_bfloat162 l23; l23.x = ml[2]; l23.y = ml[3];
        *(__nv_bfloat162*)(crow + c0)            = h01;
        *(__nv_bfloat162*)(crow + c0 + 2)        = h23;
        *(__nv_bfloat162*)(crow + 512 + c0)      = h01;
        *(__nv_bfloat162*)(crow + 512 + c0 + 2)  = h23;
        *(__nv_bfloat162*)(crow + 1024 + c0)     = l01;
        *(__nv_bfloat162*)(crow + 1024 + c0 + 2) = l23;
    }
}

// ---------------- kernel: output GEMM (64x128 tiles) + fused GRU epilogue -------
__global__ __launch_bounds__(256) void tgemm2_kernel(const float* __restrict__ b_out,
                                                     const float* __restrict__ hidden,
                                                     float* __restrict__ out) {
    extern __shared__ char smem[];

    float acc[2][4][4];
#pragma unroll
    for (int mt = 0; mt < 2; mt++)
#pragma unroll
        for (int nt = 0; nt < 4; nt++)
#pragma unroll
            for (int e = 0; e < 4; e++) acc[mt][nt][e] = 0.0f;

    mma_gemm_main64<1536>(g_Cext, g_Wout, smem, acc);

    const int wid = threadIdx.x >> 5, lane = threadIdx.x & 31;
    const int wm = (wid & 1) * 32, wn = (wid >> 1) * 32;
    const int gid = lane >> 2, tig = lane & 3;
#pragma unroll
    for (int mt = 0; mt < 2; mt++) {
        const int rbase = blockIdx.y * 64 + wm + mt * 16 + gid;
#pragma unroll
        for (int nt = 0; nt < 4; nt++) {
            const int c = blockIdx.x * 128 + wn + nt * 8 + 2 * tig;
            float2 bv = *(const float2*)(b_out + c);
#pragma unroll
            for (int half = 0; half < 2; half++) {
                const int r = rbase + half * 8;
                const __nv_bfloat16* crow = g_Cext + (size_t)r * 1536;
                __nv_bfloat162 qh2 = *(const __nv_bfloat162*)(crow + 256 + c);
                __nv_bfloat162 ql2 = *(const __nv_bfloat162*)(crow + 1280 + c);
                float2 sg2 = *(const float2*)(g_sg + (size_t)r * 256 + c);
                float2 ug2 = *(const float2*)(g_ug + (size_t)r * 256 + c);
                float2 h2  = *(const float2*)(hidden + (size_t)r * 256 + c);
                float q0 = __bfloat162float(qh2.x) + __bfloat162float(ql2.x);
                float q1 = __bfloat162float(qh2.y) + __bfloat162float(ql2.y);
                float v0 = acc[mt][nt][half * 2 + 0] + bv.x;
                float v1 = acc[mt][nt][half * 2 + 1] + bv.y;
                float a0 = tanhf(v0), a1 = tanhf(v1);
                float cu0 = q0 + sg2.x * a0;
                float cu1 = q1 + sg2.y * a1;
                float2 o;
                o.x = cu0 + ug2.x * (h2.x - cu0);
                o.y = cu1 + ug2.y * (h2.y - cu1);
                *(float2*)(out + (size_t)r * 256 + c) = o;
            }
        }
    }
}

// ---------------- launch ---------------------------------------------------------
extern "C" void kernel_launch(void* const* d_in, const int* in_sizes, int n_in,
                              void* d_out, int out_size) {
    const float* input_tensor = (const float*)d_in[0];  // (B, 258)
    const float* hidden       = (const float*)d_in[1];  // (B, 256)
    const float* w_ih         = (const float*)d_in[2];  // (1024, 256)
    const float* b_ih         = (const float*)d_in[3];  // (1024)
    const float* w_hh         = (const float*)d_in[4];  // (1024, 256)
    const float* b_hh         = (const float*)d_in[5];  // (1024)
    const float* w_out        = (const float*)d_in[6];  // (256, 512)
    const float* b_out        = (const float*)d_in[7];  // (256)
    const float* memory       = (const float*)d_in[8];  // (70, 70, 256)
    float* out = (float*)d_out;                         // (B, 256)

    // Host-side, idempotent, not a stream op (capture-safe).
    cudaFuncSetAttribute(tgemm1_kernel, cudaFuncAttributeMaxDynamicSharedMemorySize, SMEM_BYTES);
    cudaFuncSetAttribute(tgemm2_kernel, cudaFuncAttributeMaxDynamicSharedMemorySize, SMEM_BYTES2);

    conv_ah_kernel<<<dim3(8192, 1, 2), 256>>>(input_tensor, hidden);
    conv_w_kernel<<<dim3(512, 1, 3), 256>>>(w_ih, w_hh, w_out);
    tgemm1_kernel<<<dim3(8, 128, 2), 256, SMEM_BYTES>>>(b_ih, b_hh);
    phaseB_kernel<<<BSZ, 256>>>(input_tensor, memory);
    tgemm2_kernel<<<dim3(2, 256), 256, SMEM_BYTES2>>>(b_out, hidden, out);
}

// round 10
// speedup vs baseline: 1.3158x; 1.2584x over previous
#include <cuda_runtime.h>
#include <cuda_fp16.h>
#include <math.h>
#include <stdint.h>

// Problem constants
#define BSZ  16384
#define HD   256
#define GXD  70
#define GYD  70
#define SWIN 2
#define NKW  25   // 5x5 window

// ---------------- scratch (static device memory, no allocations) ----------------
// fp16 2-term split: A-side layout [hi | lo] (K_ext=2K), W-side [hi | hi]
// C = (A_hi + A_lo) . W_hi = A . W_hi  (dropped term A.W_lo ~ 2^-11 rel)
__device__ __align__(16) __half g_Aext[(size_t)BSZ * 512];
__device__ __align__(16) __half g_Hext[(size_t)BSZ * 512];
__device__ __align__(16) __half g_Wih [(size_t)1024 * 512];
__device__ __align__(16) __half g_Whh [(size_t)1024 * 512];
__device__ __align__(16) __half g_Wout[(size_t)256 * 1024];
__device__ __align__(16) __half g_Cext[(size_t)BSZ * 1024];  // [mixHi|qHi|mixLo|qLo]
__device__ float g_gi[(size_t)BSZ * 1024];
__device__ float g_gh[(size_t)BSZ * 1024];
__device__ float g_sg[(size_t)BSZ * 256];
__device__ float g_ug[(size_t)BSZ * 256];

__device__ __forceinline__ float sigmoidf_(float x) {
    return 1.0f / (1.0f + expf(-x));
}

__device__ __forceinline__ uint32_t smem_u32(const void* p) {
    uint32_t a;
    asm("{ .reg .u64 t; cvta.to.shared.u64 t, %1; cvt.u32.u64 %0, t; }" : "=r"(a) : "l"(p));
    return a;
}

__device__ __forceinline__ void ldsm_x4(uint32_t addr, uint32_t& r0, uint32_t& r1,
                                        uint32_t& r2, uint32_t& r3) {
    asm volatile("ldmatrix.sync.aligned.m8n8.x4.shared.b16 {%0,%1,%2,%3}, [%4];"
                 : "=r"(r0), "=r"(r1), "=r"(r2), "=r"(r3) : "r"(addr));
}

__device__ __forceinline__ void mma16816(float& d0, float& d1, float& d2, float& d3,
                                         uint32_t a0, uint32_t a1, uint32_t a2, uint32_t a3,
                                         uint32_t b0, uint32_t b1) {
    asm volatile("mma.sync.aligned.m16n8k16.row.col.f32.f16.f16.f32 "
                 "{%0,%1,%2,%3}, {%4,%5,%6,%7}, {%8,%9}, {%0,%1,%2,%3};"
                 : "+f"(d0), "+f"(d1), "+f"(d2), "+f"(d3)
                 : "r"(a0), "r"(a1), "r"(a2), "r"(a3), "r"(b0), "r"(b1));
}

#define CP_ASYNC16(dst, src) \
    asm volatile("cp.async.cg.shared.global [%0], [%1], 16;" :: "r"(dst), "l"(src))
#define CP_COMMIT() asm volatile("cp.async.commit_group;")
#define CP_WAIT2()  asm volatile("cp.async.wait_group 2;")

// Swizzled tile: 128 rows x 128B (64 halves), unit' = unit ^ (row&7). 16KB/tile.
#define TILEB   16384
#define STAGEB  32768   // A tile + B tile
#define NSTAGE  3
#define SMEM_BYTES (NSTAGE * STAGEB)

// ---------------- conversion kernels (fp32 -> 2-term fp16 split) ---------------
// A-side layout per row: [hi(K) | lo(K)]
__global__ __launch_bounds__(256) void conv_ah_kernel(const float* __restrict__ input_tensor,
                                                      const float* __restrict__ hidden) {
    size_t i = (size_t)blockIdx.x * 256 + threadIdx.x;   // BSZ*128 threads, 2 cols each
    size_t b = i >> 7;
    int c = (int)(i & 127) * 2;
    const float* src; __half* dst; int stride;
    if (blockIdx.z == 0) { src = input_tensor; dst = g_Aext; stride = 258; }
    else                 { src = hidden;       dst = g_Hext; stride = 256; }
    float2 v = *(const float2*)(src + b * stride + c);
    __half h0 = __float2half(v.x);
    __half h1 = __float2half(v.y);
    __half l0 = __float2half(v.x - __half2float(h0));
    __half l1 = __float2half(v.y - __half2float(h1));
    __half2 hh; hh.x = h0; hh.y = h1;
    __half2 ll; ll.x = l0; ll.y = l1;
    __half* d = dst + b * 512 + c;
    *(__half2*)(d)       = hh;
    *(__half2*)(d + 256) = ll;
}

// W-side layout per row: [hi(K) | hi(K)]; z selects {w_ih, w_hh, w_out}
__global__ __launch_bounds__(256) void conv_w_kernel(const float* __restrict__ w_ih,
                                                     const float* __restrict__ w_hh,
                                                     const float* __restrict__ w_out) {
    const int sel = blockIdx.z;
    const float* src = (sel == 0) ? w_ih : (sel == 1) ? w_hh : w_out;
    __half* dst = (sel == 0) ? g_Wih : (sel == 1) ? g_Whh : g_Wout;
    const int K = (sel == 2) ? 512 : 256;
    const int nblk = (sel == 2) ? 256 : 512;
    if (blockIdx.x >= nblk) return;
    size_t e = ((size_t)blockIdx.x * 256 + threadIdx.x) * 2;
    size_t r = e / (size_t)K;
    int k = (int)(e % (size_t)K);
    float2 v = *(const float2*)(src + r * K + k);
    __half2 hh;
    hh.x = __float2half(v.x);
    hh.y = __float2half(v.y);
    __half* d = dst + r * (size_t)(2 * K) + k;
    *(__half2*)(d)     = hh;
    *(__half2*)(d + K) = hh;
}

// ---------------- pipelined mma.sync GEMM mainloop (R6-proven scheme) -----------
// acc[mt][nt][4]: warp tile 32(m) x 64(n); 8 warps in 4(m) x 2(n).
template <int KEXT>
__device__ __forceinline__ void mma_gemm_main(const __half* __restrict__ A,
                                              const __half* __restrict__ W,
                                              char* smem, float (&acc)[2][8][4]) {
    const int tid = threadIdx.x;
    const int wid = tid >> 5, lane = tid & 31;
    const int wm = (wid & 3) * 32;
    const int wn = (wid >> 2) * 64;
    const uint32_t sbase = smem_u32(smem);

    // copy mapping: thread handles unit (tid&7), rows (tid>>3)+j*32
    const int crow0 = tid >> 3, cunit = tid & 7;
    const __half* ga = A + (size_t)(blockIdx.y * 128) * KEXT + cunit * 8;
    const __half* gw = W + (size_t)(blockIdx.x * 128) * KEXT + cunit * 8;

    // ldmatrix row indices (fixed per fragment slot)
    int rowA[2], rowB[4];
#pragma unroll
    for (int mt = 0; mt < 2; mt++)
        rowA[mt] = wm + mt * 16 + (lane & 8) + (lane & 7);
#pragma unroll
    for (int nt2 = 0; nt2 < 4; nt2++)
        rowB[nt2] = wn + nt2 * 16 + ((lane >> 4) & 1) * 8 + (lane & 7);
    const int uA = lane >> 4;          // 0..1
    const int uB = (lane >> 3) & 1;    // 0..1

    constexpr int NC = KEXT / 64;

    auto issue = [&](int ch) {
        const int s = ch % NSTAGE;
        const uint32_t dA = sbase + s * STAGEB;
        const uint32_t dB = dA + TILEB;
#pragma unroll
        for (int j = 0; j < 4; j++) {
            const int row = crow0 + j * 32;
            const uint32_t off = (uint32_t)row * 128 + (uint32_t)((cunit ^ (row & 7)) * 16);
            const size_t gofs = (size_t)row * KEXT + ch * 64;
            CP_ASYNC16(dA + off, ga + gofs);
            CP_ASYNC16(dB + off, gw + gofs);
        }
        CP_COMMIT();
    };

    issue(0);
    issue(1);
#pragma unroll 1
    for (int ch = 0; ch < NC; ch++) {
        if (ch + 2 < NC) issue(ch + 2); else CP_COMMIT();
        CP_WAIT2();
        __syncthreads();
        const int s = ch % NSTAGE;
        const uint32_t aB = sbase + s * STAGEB;
        const uint32_t bB = aB + TILEB;
#pragma unroll
        for (int ks = 0; ks < 4; ks++) {
            uint32_t a[2][4], b[4][4];
#pragma unroll
            for (int mt = 0; mt < 2; mt++) {
                const int u = ks * 2 + uA;
                const uint32_t addr = aB + (uint32_t)rowA[mt] * 128
                                    + (uint32_t)((u ^ (rowA[mt] & 7)) * 16);
                ldsm_x4(addr, a[mt][0], a[mt][1], a[mt][2], a[mt][3]);
            }
#pragma unroll
            for (int nt2 = 0; nt2 < 4; nt2++) {
                const int u = ks * 2 + uB;
                const uint32_t addr = bB + (uint32_t)rowB[nt2] * 128
                                    + (uint32_t)((u ^ (rowB[nt2] & 7)) * 16);
                ldsm_x4(addr, b[nt2][0], b[nt2][1], b[nt2][2], b[nt2][3]);
            }
#pragma unroll
            for (int mt = 0; mt < 2; mt++)
#pragma unroll
                for (int nt = 0; nt < 8; nt++) {
                    const uint32_t b0 = b[nt >> 1][(nt & 1) * 2 + 0];
                    const uint32_t b1 = b[nt >> 1][(nt & 1) * 2 + 1];
                    mma16816(acc[mt][nt][0], acc[mt][nt][1], acc[mt][nt][2], acc[mt][nt][3],
                             a[mt][0], a[mt][1], a[mt][2], a[mt][3], b0, b1);
                }
        }
        __syncthreads();
    }
}

// ---------------- kernel: gi / gh GEMMs (z=0: feature, z=1: hidden) -------------
__global__ __launch_bounds__(256) void tgemm1_kernel(const float* __restrict__ b_ih,
                                                     const float* __restrict__ b_hh) {
    extern __shared__ char smem[];
    const __half* A = blockIdx.z ? g_Hext : g_Aext;
    const __half* W = blockIdx.z ? g_Whh  : g_Wih;
    const float* bias = blockIdx.z ? b_hh : b_ih;
    float* C          = blockIdx.z ? g_gh : g_gi;

    float acc[2][8][4];
#pragma unroll
    for (int mt = 0; mt < 2; mt++)
#pragma unroll
        for (int nt = 0; nt < 8; nt++)
#pragma unroll
            for (int e = 0; e < 4; e++) acc[mt][nt][e] = 0.0f;

    mma_gemm_main<512>(A, W, smem, acc);

    const int wid = threadIdx.x >> 5, lane = threadIdx.x & 31;
    const int wm = (wid & 3) * 32, wn = (wid >> 2) * 64;
    const int gid = lane >> 2, tig = lane & 3;
#pragma unroll
    for (int mt = 0; mt < 2; mt++) {
        const int r = blockIdx.y * 128 + wm + mt * 16 + gid;
#pragma unroll
        for (int nt = 0; nt < 8; nt++) {
            const int c = blockIdx.x * 128 + wn + nt * 8 + 2 * tig;
            float2 bv = *(const float2*)(bias + c);
            float2 v0 = { acc[mt][nt][0] + bv.x, acc[mt][nt][1] + bv.y };
            float2 v1 = { acc[mt][nt][2] + bv.x, acc[mt][nt][3] + bv.y };
            *(float2*)(C + (size_t)r * 1024 + c)       = v0;
            *(float2*)(C + (size_t)(r + 8) * 1024 + c) = v1;
        }
    }
}

// ---------------- kernel: gates + attention over 5x5 context (R6-proven) -------
__global__ __launch_bounds__(256) void phaseB_kernel(
    const float* __restrict__ input_tensor,
    const float* __restrict__ memory) {
    const int b = blockIdx.x;
    const int t = threadIdx.x;

    __shared__ float q_s[HD];
    __shared__ float ctx[NKW][HD];
    __shared__ float attn_p[NKW][2];
    __shared__ float w_s[NKW];

    const float* gi = g_gi + (size_t)b * 1024;
    const float* gh = g_gh + (size_t)b * 1024;
    float i_r = gi[t],       h_r = gh[t];
    float i_i = gi[256 + t], h_i = gh[256 + t];
    float i_n = gi[512 + t], h_n = gh[512 + t];
    float i_s = gi[768 + t], h_s = gh[768 + t];

    float rg = sigmoidf_(i_r + h_r);
    float ug = sigmoidf_(i_i + h_i);
    float sg = sigmoidf_(i_s + h_s);
    float q  = tanhf(i_n + rg * h_n);
    q_s[t] = q;
    g_sg[(size_t)b * HD + t] = sg;
    g_ug[(size_t)b * HD + t] = ug;

    int gx = (int)input_tensor[(size_t)b * 258 + 256] + SWIN;
    int gy = (int)input_tensor[(size_t)b * 258 + 257] + SWIN;
    gx = min(max(gx, 0), GXD - 1);
    gy = min(max(gy, 0), GYD - 1);

    __syncthreads();   // q_s ready for the fused dot

    // fused gather + partial attention dot (float4); 64 threads per k-row
    const int kq  = t >> 6;          // 0..3 row group
    const int cq  = (t & 63) * 4;    // float4 column base
    const int lane = t & 31;
    const int sub  = (t >> 5) & 1;
    float4 q4 = *(const float4*)(q_s + cq);
#pragma unroll
    for (int base = 0; base < 28; base += 4) {
        const int k = base + kq;
        if (k < NKW) {               // uniform per warp (64-thread groups)
            int xi = min(max(gx + k / 5 - SWIN, 0), GXD - 1);
            int yi = min(max(gy + k % 5 - SWIN, 0), GYD - 1);
            float4 v = *(const float4*)(memory + ((size_t)xi * GYD + yi) * HD + cq);
            *(float4*)(&ctx[k][cq]) = v;
            float part = v.x * q4.x + v.y * q4.y + v.z * q4.z + v.w * q4.w;
#pragma unroll
            for (int off = 16; off; off >>= 1)
                part += __shfl_xor_sync(0xffffffffu, part, off);
            if (lane == 0) attn_p[k][sub] = part;
        }
    }
    __syncthreads();

    // softmax over 25 (one warp), attn==0 -> -inf, NaN -> 0 semantics
    if (t < 32) {
        float v = (lane < NKW) ? (attn_p[lane][0] + attn_p[lane][1]) : -INFINITY;
        if (v == 0.0f) v = -INFINITY;
        float mx = v;
#pragma unroll
        for (int off = 16; off; off >>= 1)
            mx = fmaxf(mx, __shfl_xor_sync(0xffffffffu, mx, off));
        float e = (mx == -INFINITY) ? 0.0f : expf(v - mx);
        float den = e;
#pragma unroll
        for (int off = 16; off; off >>= 1)
            den += __shfl_xor_sync(0xffffffffu, den, off);
        float wv = (den > 0.0f) ? (e / den) : 0.0f;
        if (lane < NKW) w_s[lane] = wv;
    }
    __syncthreads();

    // mix = sum_k w_k * ctx[k][:]
    float mix = 0.0f;
#pragma unroll
    for (int k = 0; k < NKW; k++)
        mix = fmaf(w_s[k], ctx[k][t], mix);

    // write combined = [mix | q] as 2-term fp16 split (A-side layout)
    __half mh = __float2half(mix);
    __half ml = __float2half(mix - __half2float(mh));
    __half qh = __float2half(q);
    __half ql = __float2half(q - __half2float(qh));
    __half* crow = g_Cext + (size_t)b * 1024;
    crow[t]        = mh;   // mixHi
    crow[256 + t]  = qh;   // qHi
    crow[512 + t]  = ml;   // mixLo
    crow[768 + t]  = ql;   // qLo
}

// ---------------- kernel: output GEMM + fused GRU epilogue ----------------------
__global__ __launch_bounds__(256) void tgemm2_kernel(const float* __restrict__ b_out,
                                                     const float* __restrict__ hidden,
                                                     float* __restrict__ out) {
    extern __shared__ char smem[];

    float acc[2][8][4];
#pragma unroll
    for (int mt = 0; mt < 2; mt++)
#pragma unroll
        for (int nt = 0; nt < 8; nt++)
#pragma unroll
            for (int e = 0; e < 4; e++) acc[mt][nt][e] = 0.0f;

    mma_gemm_main<1024>(g_Cext, g_Wout, smem, acc);

    const int wid = threadIdx.x >> 5, lane = threadIdx.x & 31;
    const int wm = (wid & 3) * 32, wn = (wid >> 2) * 64;
    const int gid = lane >> 2, tig = lane & 3;
#pragma unroll
    for (int mt = 0; mt < 2; mt++) {
        const int rbase = blockIdx.y * 128 + wm + mt * 16 + gid;
#pragma unroll
        for (int nt = 0; nt < 8; nt++) {
            const int c = blockIdx.x * 128 + wn + nt * 8 + 2 * tig;
            float2 bv = *(const float2*)(b_out + c);
#pragma unroll
            for (int half = 0; half < 2; half++) {
                const int r = rbase + half * 8;
                const __half* crow = g_Cext + (size_t)r * 1024;
                __half2 qh2 = *(const __half2*)(crow + 256 + c);
                __half2 ql2 = *(const __half2*)(crow + 768 + c);
                float2 sg2 = *(const float2*)(g_sg + (size_t)r * 256 + c);
                float2 ug2 = *(const float2*)(g_ug + (size_t)r * 256 + c);
                float2 h2  = *(const float2*)(hidden + (size_t)r * 256 + c);
                float q0 = __half2float(qh2.x) + __half2float(ql2.x);
                float q1 = __half2float(qh2.y) + __half2float(ql2.y);
                float v0 = acc[mt][nt][half * 2 + 0] + bv.x;
                float v1 = acc[mt][nt][half * 2 + 1] + bv.y;
                float a0 = tanhf(v0), a1 = tanhf(v1);
                float cu0 = q0 + sg2.x * a0;
                float cu1 = q1 + sg2.y * a1;
                float2 o;
                o.x = cu0 + ug2.x * (h2.x - cu0);
                o.y = cu1 + ug2.y * (h2.y - cu1);
                *(float2*)(out + (size_t)r * 256 + c) = o;
            }
        }
    }
}

// ---------------- launch ---------------------------------------------------------
extern "C" void kernel_launch(void* const* d_in, const int* in_sizes, int n_in,
                              void* d_out, int out_size) {
    const float* input_tensor = (const float*)d_in[0];  // (B, 258)
    const float* hidden       = (const float*)d_in[1];  // (B, 256)
    const float* w_ih         = (const float*)d_in[2];  // (1024, 256)
    const float* b_ih         = (const float*)d_in[3];  // (1024)
    const float* w_hh         = (const float*)d_in[4];  // (1024, 256)
    const float* b_hh         = (const float*)d_in[5];  // (1024)
    const float* w_out        = (const float*)d_in[6];  // (256, 512)
    const float* b_out        = (const float*)d_in[7];  // (256)
    const float* memory       = (const float*)d_in[8];  // (70, 70, 256)
    float* out = (float*)d_out;                         // (B, 256)

    // Host-side, idempotent, not a stream op (capture-safe).
    cudaFuncSetAttribute(tgemm1_kernel, cudaFuncAttributeMaxDynamicSharedMemorySize, SMEM_BYTES);
    cudaFuncSetAttribute(tgemm2_kernel, cudaFuncAttributeMaxDynamicSharedMemorySize, SMEM_BYTES);

    conv_ah_kernel<<<dim3(8192, 1, 2), 256>>>(input_tensor, hidden);
    conv_w_kernel<<<dim3(512, 1, 3), 256>>>(w_ih, w_hh, w_out);
    tgemm1_kernel<<<dim3(8, 128, 2), 256, SMEM_BYTES>>>(b_ih, b_hh);
    phaseB_kernel<<<BSZ, 256>>>(input_tensor, memory);
    tgemm2_kernel<<<dim3(2, 128), 256, SMEM_BYTES>>>(b_out, hidden, out);
}

// round 12
// speedup vs baseline: 1.3228x; 1.0053x over previous
#include <cuda_runtime.h>
#include <cuda_fp16.h>
#include <math.h>
#include <stdint.h>

// Problem constants
#define BSZ  16384
#define HD   256
#define GXD  70
#define GYD  70
#define SWIN 2
#define NKW  25   // 5x5 window

// ---------------- scratch (static device memory, no allocations) ----------------
// fp16 2-term split: A-side layout [hi | lo] (K_ext=2K), W-side [hi | hi]
// C = (A_hi + A_lo) . W_hi = A . W_hi  (dropped term A.W_lo ~ 2^-11 rel)
__device__ __align__(16) __half g_Aext[(size_t)BSZ * 512];
__device__ __align__(16) __half g_Hext[(size_t)BSZ * 512];
__device__ __align__(16) __half g_Wih [(size_t)1024 * 512];
__device__ __align__(16) __half g_Whh [(size_t)1024 * 512];
__device__ __align__(16) __half g_Wout[(size_t)256 * 1024];
__device__ __align__(16) __half g_Cext[(size_t)BSZ * 1024];  // [mixHi|qHi|mixLo|qLo]
__device__ float g_gi[(size_t)BSZ * 1024];
__device__ float g_gh[(size_t)BSZ * 1024];
__device__ float g_sg[(size_t)BSZ * 256];
__device__ float g_ug[(size_t)BSZ * 256];

__device__ __forceinline__ float sigmoidf_(float x) {
    return 1.0f / (1.0f + expf(-x));
}

__device__ __forceinline__ uint32_t smem_u32(const void* p) {
    uint32_t a;
    asm("{ .reg .u64 t; cvta.to.shared.u64 t, %1; cvt.u32.u64 %0, t; }" : "=r"(a) : "l"(p));
    return a;
}

__device__ __forceinline__ void ldsm_x4(uint32_t addr, uint32_t& r0, uint32_t& r1,
                                        uint32_t& r2, uint32_t& r3) {
    asm volatile("ldmatrix.sync.aligned.m8n8.x4.shared.b16 {%0,%1,%2,%3}, [%4];"
                 : "=r"(r0), "=r"(r1), "=r"(r2), "=r"(r3) : "r"(addr));
}

__device__ __forceinline__ void mma16816(float& d0, float& d1, float& d2, float& d3,
                                         uint32_t a0, uint32_t a1, uint32_t a2, uint32_t a3,
                                         uint32_t b0, uint32_t b1) {
    asm volatile("mma.sync.aligned.m16n8k16.row.col.f32.f16.f16.f32 "
                 "{%0,%1,%2,%3}, {%4,%5,%6,%7}, {%8,%9}, {%0,%1,%2,%3};"
                 : "+f"(d0), "+f"(d1), "+f"(d2), "+f"(d3)
                 : "r"(a0), "r"(a1), "r"(a2), "r"(a3), "r"(b0), "r"(b1));
}

#define CP_ASYNC16(dst, src) \
    asm volatile("cp.async.cg.shared.global [%0], [%1], 16;" :: "r"(dst), "l"(src))
#define CP_COMMIT() asm volatile("cp.async.commit_group;")
#define CP_WAIT2()  asm volatile("cp.async.wait_group 2;")

// Swizzled tile: 128 rows x 128B (64 halves), unit' = unit ^ (row&7). 16KB/tile.
#define TILEB   16384
#define STAGEB  32768   // A tile + B tile
#define NSTAGE  3
#define SMEM_BYTES (NSTAGE * STAGEB)

// ---------------- conversion kernels (fp32 -> 2-term fp16 split) ---------------
// A-side layout per row: [hi(K) | lo(K)]
__global__ __launch_bounds__(256) void conv_ah_kernel(const float* __restrict__ input_tensor,
                                                      const float* __restrict__ hidden) {
    size_t i = (size_t)blockIdx.x * 256 + threadIdx.x;   // BSZ*128 threads, 2 cols each
    size_t b = i >> 7;
    int c = (int)(i & 127) * 2;
    const float* src; __half* dst; int stride;
    if (blockIdx.z == 0) { src = input_tensor; dst = g_Aext; stride = 258; }
    else                 { src = hidden;       dst = g_Hext; stride = 256; }
    float2 v = *(const float2*)(src + b * stride + c);
    __half h0 = __float2half(v.x);
    __half h1 = __float2half(v.y);
    __half l0 = __float2half(v.x - __half2float(h0));
    __half l1 = __float2half(v.y - __half2float(h1));
    __half2 hh; hh.x = h0; hh.y = h1;
    __half2 ll; ll.x = l0; ll.y = l1;
    __half* d = dst + b * 512 + c;
    *(__half2*)(d)       = hh;
    *(__half2*)(d + 256) = ll;
}

// W-side layout per row: [hi(K) | hi(K)]; z selects {w_ih, w_hh, w_out}
__global__ __launch_bounds__(256) void conv_w_kernel(const float* __restrict__ w_ih,
                                                     const float* __restrict__ w_hh,
                                                     const float* __restrict__ w_out) {
    const int sel = blockIdx.z;
    const float* src = (sel == 0) ? w_ih : (sel == 1) ? w_hh : w_out;
    __half* dst = (sel == 0) ? g_Wih : (sel == 1) ? g_Whh : g_Wout;
    const int K = (sel == 2) ? 512 : 256;
    const int nblk = (sel == 2) ? 256 : 512;
    if (blockIdx.x >= nblk) return;
    size_t e = ((size_t)blockIdx.x * 256 + threadIdx.x) * 2;
    size_t r = e / (size_t)K;
    int k = (int)(e % (size_t)K);
    float2 v = *(const float2*)(src + r * K + k);
    __half2 hh;
    hh.x = __float2half(v.x);
    hh.y = __float2half(v.y);
    __half* d = dst + r * (size_t)(2 * K) + k;
    *(__half2*)(d)     = hh;
    *(__half2*)(d + K) = hh;
}

// ---------------- pipelined mma.sync GEMM mainloop (proven scheme) --------------
// acc[mt][nt][4]: warp tile 32(m) x 64(n); 8 warps in 4(m) x 2(n).
template <int KEXT>
__device__ __forceinline__ void mma_gemm_main(const __half* __restrict__ A,
                                              const __half* __restrict__ W,
                                              char* smem, float (&acc)[2][8][4]) {
    const int tid = threadIdx.x;
    const int wid = tid >> 5, lane = tid & 31;
    const int wm = (wid & 3) * 32;
    const int wn = (wid >> 2) * 64;
    const uint32_t sbase = smem_u32(smem);

    const int crow0 = tid >> 3, cunit = tid & 7;
    const __half* ga = A + (size_t)(blockIdx.y * 128) * KEXT + cunit * 8;
    const __half* gw = W + (size_t)(blockIdx.x * 128) * KEXT + cunit * 8;

    int rowA[2], rowB[4];
#pragma unroll
    for (int mt = 0; mt < 2; mt++)
        rowA[mt] = wm + mt * 16 + (lane & 8) + (lane & 7);
#pragma unroll
    for (int nt2 = 0; nt2 < 4; nt2++)
        rowB[nt2] = wn + nt2 * 16 + ((lane >> 4) & 1) * 8 + (lane & 7);
    const int uA = lane >> 4;          // 0..1
    const int uB = (lane >> 3) & 1;    // 0..1

    constexpr int NC = KEXT / 64;

    auto issue = [&](int ch) {
        const int s = ch % NSTAGE;
        const uint32_t dA = sbase + s * STAGEB;
        const uint32_t dB = dA + TILEB;
#pragma unroll
        for (int j = 0; j < 4; j++) {
            const int row = crow0 + j * 32;
            const uint32_t off = (uint32_t)row * 128 + (uint32_t)((cunit ^ (row & 7)) * 16);
            const size_t gofs = (size_t)row * KEXT + ch * 64;
            CP_ASYNC16(dA + off, ga + gofs);
            CP_ASYNC16(dB + off, gw + gofs);
        }
        CP_COMMIT();
    };

    issue(0);
    issue(1);
#pragma unroll 1
    for (int ch = 0; ch < NC; ch++) {
        if (ch + 2 < NC) issue(ch + 2); else CP_COMMIT();
        CP_WAIT2();
        __syncthreads();
        const int s = ch % NSTAGE;
        const uint32_t aB = sbase + s * STAGEB;
        const uint32_t bB = aB + TILEB;
#pragma unroll
        for (int ks = 0; ks < 4; ks++) {
            uint32_t a[2][4], b[4][4];
#pragma unroll
            for (int mt = 0; mt < 2; mt++) {
                const int u = ks * 2 + uA;
                const uint32_t addr = aB + (uint32_t)rowA[mt] * 128
                                    + (uint32_t)((u ^ (rowA[mt] & 7)) * 16);
                ldsm_x4(addr, a[mt][0], a[mt][1], a[mt][2], a[mt][3]);
            }
#pragma unroll
            for (int nt2 = 0; nt2 < 4; nt2++) {
                const int u = ks * 2 + uB;
                const uint32_t addr = bB + (uint32_t)rowB[nt2] * 128
                                    + (uint32_t)((u ^ (rowB[nt2] & 7)) * 16);
                ldsm_x4(addr, b[nt2][0], b[nt2][1], b[nt2][2], b[nt2][3]);
            }
#pragma unroll
            for (int mt = 0; mt < 2; mt++)
#pragma unroll
                for (int nt = 0; nt < 8; nt++) {
                    const uint32_t b0 = b[nt >> 1][(nt & 1) * 2 + 0];
                    const uint32_t b1 = b[nt >> 1][(nt & 1) * 2 + 1];
                    mma16816(acc[mt][nt][0], acc[mt][nt][1], acc[mt][nt][2], acc[mt][nt][3],
                             a[mt][0], a[mt][1], a[mt][2], a[mt][3], b0, b1);
                }
        }
        __syncthreads();
    }
}

// ---------------- kernel: gi / gh GEMMs (z=0: feature, z=1: hidden) -------------
__global__ __launch_bounds__(256) void tgemm1_kernel(const float* __restrict__ b_ih,
                                                     const float* __restrict__ b_hh) {
    extern __shared__ char smem[];
    const __half* A = blockIdx.z ? g_Hext : g_Aext;
    const __half* W = blockIdx.z ? g_Whh  : g_Wih;
    const float* bias = blockIdx.z ? b_hh : b_ih;
    float* C          = blockIdx.z ? g_gh : g_gi;

    float acc[2][8][4];
#pragma unroll
    for (int mt = 0; mt < 2; mt++)
#pragma unroll
        for (int nt = 0; nt < 8; nt++)
#pragma unroll
            for (int e = 0; e < 4; e++) acc[mt][nt][e] = 0.0f;

    mma_gemm_main<512>(A, W, smem, acc);

    const int wid = threadIdx.x >> 5, lane = threadIdx.x & 31;
    const int wm = (wid & 3) * 32, wn = (wid >> 2) * 64;
    const int gid = lane >> 2, tig = lane & 3;
#pragma unroll
    for (int mt = 0; mt < 2; mt++) {
        const int r = blockIdx.y * 128 + wm + mt * 16 + gid;
#pragma unroll
        for (int nt = 0; nt < 8; nt++) {
            const int c = blockIdx.x * 128 + wn + nt * 8 + 2 * tig;
            float2 bv = *(const float2*)(bias + c);
            float2 v0 = { acc[mt][nt][0] + bv.x, acc[mt][nt][1] + bv.y };
            float2 v1 = { acc[mt][nt][2] + bv.x, acc[mt][nt][3] + bv.y };
            *(float2*)(C + (size_t)r * 1024 + c)       = v0;
            *(float2*)(C + (size_t)(r + 8) * 1024 + c) = v1;
        }
    }
}

// ---------------- kernel: gates + attention over 5x5 context -------------------
// Two-pass gather (no ctx smem): pass1 fused gather+dot, pass2 re-gather+mix.
__global__ __launch_bounds__(256) void phaseB_kernel(
    const float* __restrict__ input_tensor,
    const float* __restrict__ memory) {
    const int b = blockIdx.x;
    const int t = threadIdx.x;

    __shared__ __align__(16) float q_s[HD];
    __shared__ __align__(16) float attn_p[NKW][2];
    __shared__ __align__(16) float w_s[NKW];
    __shared__ __align__(16) float mixp[4][HD];   // per-k-group mix partials

    const float* gi = g_gi + (size_t)b * 1024;
    const float* gh = g_gh + (size_t)b * 1024;
    float i_r = gi[t],       h_r = gh[t];
    float i_i = gi[256 + t], h_i = gh[256 + t];
    float i_n = gi[512 + t], h_n = gh[512 + t];
    float i_s = gi[768 + t], h_s = gh[768 + t];

    float rg = sigmoidf_(i_r + h_r);
    float ug = sigmoidf_(i_i + h_i);
    float sg = sigmoidf_(i_s + h_s);
    float q  = tanhf(i_n + rg * h_n);
    q_s[t] = q;
    g_sg[(size_t)b * HD + t] = sg;
    g_ug[(size_t)b * HD + t] = ug;

    int gx = (int)input_tensor[(size_t)b * 258 + 256] + SWIN;
    int gy = (int)input_tensor[(size_t)b * 258 + 257] + SWIN;
    gx = min(max(gx, 0), GXD - 1);
    gy = min(max(gy, 0), GYD - 1);

    __syncthreads();   // q_s ready for the fused dot

    // pass 1: fused gather + partial attention dot (float4); 64 threads per k-row
    const int kq  = t >> 6;          // 0..3 k-group
    const int cq  = (t & 63) * 4;    // float4 column base
    const int lane = t & 31;
    const int sub  = (t >> 5) & 1;
    float4 q4 = *(const float4*)(q_s + cq);
#pragma unroll
    for (int base = 0; base < 28; base += 4) {
        const int k = base + kq;
        if (k < NKW) {               // uniform per warp (64-thread groups)
            int xi = min(max(gx + k / 5 - SWIN, 0), GXD - 1);
            int yi = min(max(gy + k % 5 - SWIN, 0), GYD - 1);
            float4 v = *(const float4*)(memory + ((size_t)xi * GYD + yi) * HD + cq);
            float part = v.x * q4.x + v.y * q4.y + v.z * q4.z + v.w * q4.w;
#pragma unroll
            for (int off = 16; off; off >>= 1)
                part += __shfl_xor_sync(0xffffffffu, part, off);
            if (lane == 0) attn_p[k][sub] = part;
        }
    }
    __syncthreads();

    // softmax over 25 (one warp), attn==0 -> -inf, NaN -> 0 semantics
    if (t < 32) {
        float v = (lane < NKW) ? (attn_p[lane][0] + attn_p[lane][1]) : -INFINITY;
        if (v == 0.0f) v = -INFINITY;
        float mx = v;
#pragma unroll
        for (int off = 16; off; off >>= 1)
            mx = fmaxf(mx, __shfl_xor_sync(0xffffffffu, mx, off));
        float e = (mx == -INFINITY) ? 0.0f : expf(v - mx);
        float den = e;
#pragma unroll
        for (int off = 16; off; off >>= 1)
            den += __shfl_xor_sync(0xffffffffu, den, off);
        float wv = (den > 0.0f) ? (e / den) : 0.0f;
        if (lane < NKW) w_s[lane] = wv;
    }

    // q-dependent Cext writes (independent of mix)
    __half* crow = g_Cext + (size_t)b * 1024;
    {
        __half qh = __float2half(q);
        __half ql = __float2half(q - __half2float(qh));
        crow[256 + t] = qh;   // qHi
        crow[768 + t] = ql;   // qLo
    }
    __syncthreads();

    // pass 2: re-gather (L2/L1 hits) + weighted mix partials per k-group
    {
        float4 m4 = make_float4(0.0f, 0.0f, 0.0f, 0.0f);
#pragma unroll
        for (int base = 0; base < 28; base += 4) {
            const int k = base + kq;
            if (k < NKW) {
                int xi = min(max(gx + k / 5 - SWIN, 0), GXD - 1);
                int yi = min(max(gy + k % 5 - SWIN, 0), GYD - 1);
                float4 v = *(const float4*)(memory + ((size_t)xi * GYD + yi) * HD + cq);
                const float w = w_s[k];
                m4.x = fmaf(w, v.x, m4.x);
                m4.y = fmaf(w, v.y, m4.y);
                m4.z = fmaf(w, v.z, m4.z);
                m4.w = fmaf(w, v.w, m4.w);
            }
        }
        *(float4*)(&mixp[kq][cq]) = m4;
    }
    __syncthreads();

    // combine 4 k-group partials (64 threads) and write mix split
    if (t < 64) {
        const int c0 = t * 4;
        float4 a0 = *(const float4*)(&mixp[0][c0]);
        float4 a1 = *(const float4*)(&mixp[1][c0]);
        float4 a2 = *(const float4*)(&mixp[2][c0]);
        float4 a3 = *(const float4*)(&mixp[3][c0]);
        float mv[4] = { a0.x + a1.x + a2.x + a3.x,
                        a0.y + a1.y + a2.y + a3.y,
                        a0.z + a1.z + a2.z + a3.z,
                        a0.w + a1.w + a2.w + a3.w };
        __half mh[4], ml[4];
#pragma unroll
        for (int e = 0; e < 4; e++) {
            mh[e] = __float2half(mv[e]);
            ml[e] = __float2half(mv[e] - __half2float(mh[e]));
        }
        __half2 h01; h01.x = mh[0]; h01.y = mh[1];
        __half2 h23; h23.x = mh[2]; h23.y = mh[3];
        __half2 l01; l01.x = ml[0]; l01.y = ml[1];
        __half2 l23; l23.x = ml[2]; l23.y = ml[3];
        *(__half2*)(crow + c0)           = h01;   // mixHi
        *(__half2*)(crow + c0 + 2)       = h23;
        *(__half2*)(crow + 512 + c0)     = l01;   // mixLo
        *(__half2*)(crow + 512 + c0 + 2) = l23;
    }
}

// ---------------- kernel: output GEMM + fused GRU epilogue ----------------------
__global__ __launch_bounds__(256) void tgemm2_kernel(const float* __restrict__ b_out,
                                                     const float* __restrict__ hidden,
                                                     float* __restrict__ out) {
    extern __shared__ char smem[];

    float acc[2][8][4];
#pragma unroll
    for (int mt = 0; mt < 2; mt++)
#pragma unroll
        for (int nt = 0; nt < 8; nt++)
#pragma unroll
            for (int e = 0; e < 4; e++) acc[mt][nt][e] = 0.0f;

    mma_gemm_main<1024>(g_Cext, g_Wout, smem, acc);

    const int wid = threadIdx.x >> 5, lane = threadIdx.x & 31;
    const int wm = (wid & 3) * 32, wn = (wid >> 2) * 64;
    const int gid = lane >> 2, tig = lane & 3;
#pragma unroll
    for (int mt = 0; mt < 2; mt++) {
        const int rbase = blockIdx.y * 128 + wm + mt * 16 + gid;
#pragma unroll
        for (int nt = 0; nt < 8; nt++) {
            const int c = blockIdx.x * 128 + wn + nt * 8 + 2 * tig;
            float2 bv = *(const float2*)(b_out + c);
#pragma unroll
            for (int half = 0; half < 2; half++) {
                const int r = rbase + half * 8;
                const __half* crow = g_Cext + (size_t)r * 1024;
                __half2 qh2 = *(const __half2*)(crow + 256 + c);
                __half2 ql2 = *(const __half2*)(crow + 768 + c);
                float2 sg2 = *(const float2*)(g_sg + (size_t)r * 256 + c);
                float2 ug2 = *(const float2*)(g_ug + (size_t)r * 256 + c);
                float2 h2  = *(const float2*)(hidden + (size_t)r * 256 + c);
                float q0 = __half2float(qh2.x) + __half2float(ql2.x);
                float q1 = __half2float(qh2.y) + __half2float(ql2.y);
                float v0 = acc[mt][nt][half * 2 + 0] + bv.x;
                float v1 = acc[mt][nt][half * 2 + 1] + bv.y;
                float a0 = tanhf(v0), a1 = tanhf(v1);
                float cu0 = q0 + sg2.x * a0;
                float cu1 = q1 + sg2.y * a1;
                float2 o;
                o.x = cu0 + ug2.x * (h2.x - cu0);
                o.y = cu1 + ug2.y * (h2.y - cu1);
                *(float2*)(out + (size_t)r * 256 + c) = o;
            }
        }
    }
}

// ---------------- launch ---------------------------------------------------------
extern "C" void kernel_launch(void* const* d_in, const int* in_sizes, int n_in,
                              void* d_out, int out_size) {
    const float* input_tensor = (const float*)d_in[0];  // (B, 258)
    const float* hidden       = (const float*)d_in[1];  // (B, 256)
    const float* w_ih         = (const float*)d_in[2];  // (1024, 256)
    const float* b_ih         = (const float*)d_in[3];  // (1024)
    const float* w_hh         = (const float*)d_in[4];  // (1024, 256)
    const float* b_hh         = (const float*)d_in[5];  // (1024)
    const float* w_out        = (const float*)d_in[6];  // (256, 512)
    const float* b_out        = (const float*)d_in[7];  // (256)
    const float* memory       = (const float*)d_in[8];  // (70, 70, 256)
    float* out = (float*)d_out;                         // (B, 256)

    // Host-side, idempotent, not a stream op (capture-safe).
    cudaFuncSetAttribute(tgemm1_kernel, cudaFuncAttributeMaxDynamicSharedMemorySize, SMEM_BYTES);
    cudaFuncSetAttribute(tgemm2_kernel, cudaFuncAttributeMaxDynamicSharedMemorySize, SMEM_BYTES);

    conv_ah_kernel<<<dim3(8192, 1, 2), 256>>>(input_tensor, hidden);
    conv_w_kernel<<<dim3(512, 1, 3), 256>>>(w_ih, w_hh, w_out);
    tgemm1_kernel<<<dim3(8, 128, 2), 256, SMEM_BYTES>>>(b_ih, b_hh);
    phaseB_kernel<<<BSZ, 256>>>(input_tensor, memory);
    tgemm2_kernel<<<dim3(2, 128), 256, SMEM_BYTES>>>(b_out, hidden, out);
}